// round 7
// baseline (speedup 1.0000x reference)
#include <cuda_runtime.h>
#include <cuda_fp16.h>
#include <cstdint>

#define MAX_NODES 100000
#define D 128
#define EPT 7           // edges per thread (edge kernel)
#define EBLK 1024       // threads per block (edge kernel)

#define TABLE_BYTES (MAX_NODES * 2)      // fp16 s-table = 200000 B
#define SMEM_TABLE_OFF 16                // mbarrier at 0, table at 16
#define SMEM_TOTAL (SMEM_TABLE_OFF + TABLE_BYTES)

// Per-node projections: s as fp16 (smem-table source), d as fp32 with bias folded in.
__device__ __half g_s_h[MAX_NODES];
__device__ float  g_d[MAX_NODES];

__device__ __forceinline__ uint32_t smem_u32(const void* p) {
    uint32_t a;
    asm("{ .reg .u64 t; cvta.to.shared.u64 t, %1; cvt.u32.u64 %0, t; }" : "=r"(a) : "l"(p));
    return a;
}

// Kernel 1: 4 nodes per warp, all loads issued up-front for MLP=4.
__global__ void node_dots_kernel(const float4* __restrict__ x4,
                                 const float* __restrict__ W,
                                 const float* __restrict__ b,
                                 int n_nodes) {
    __shared__ float4 ws4[32];
    __shared__ float4 wd4[32];
    int tid = threadIdx.x;
    if (tid < 32) ws4[tid] = ((const float4*)W)[tid];
    else if (tid < 64) wd4[tid - 32] = ((const float4*)W)[tid - 32 + 32];
    __syncthreads();

    int lane = tid & 31;
    int gwarp = (blockIdx.x * blockDim.x + tid) >> 5;
    int base = gwarp * 4;
    if (base >= n_nodes) return;

    float4 a = ws4[lane];
    float4 c = wd4[lane];

    int n1 = base + 1, n2 = base + 2, n3 = base + 3;
    bool h1 = n1 < n_nodes, h2 = n2 < n_nodes, h3 = n3 < n_nodes;
    float4 v0 = x4[(size_t)base * 32 + lane];
    float4 v1 = h1 ? x4[(size_t)n1 * 32 + lane] : make_float4(0.f, 0.f, 0.f, 0.f);
    float4 v2 = h2 ? x4[(size_t)n2 * 32 + lane] : make_float4(0.f, 0.f, 0.f, 0.f);
    float4 v3 = h3 ? x4[(size_t)n3 * 32 + lane] : make_float4(0.f, 0.f, 0.f, 0.f);

    float s0 = v0.x * a.x + v0.y * a.y + v0.z * a.z + v0.w * a.w;
    float d0 = v0.x * c.x + v0.y * c.y + v0.z * c.z + v0.w * c.w;
    float s1 = v1.x * a.x + v1.y * a.y + v1.z * a.z + v1.w * a.w;
    float d1 = v1.x * c.x + v1.y * c.y + v1.z * c.z + v1.w * c.w;
    float s2 = v2.x * a.x + v2.y * a.y + v2.z * a.z + v2.w * a.w;
    float d2 = v2.x * c.x + v2.y * c.y + v2.z * c.z + v2.w * c.w;
    float s3 = v3.x * a.x + v3.y * a.y + v3.z * a.z + v3.w * a.w;
    float d3 = v3.x * c.x + v3.y * c.y + v3.z * c.z + v3.w * c.w;

    #pragma unroll
    for (int off = 16; off > 0; off >>= 1) {
        s0 += __shfl_down_sync(0xFFFFFFFFu, s0, off);
        d0 += __shfl_down_sync(0xFFFFFFFFu, d0, off);
        s1 += __shfl_down_sync(0xFFFFFFFFu, s1, off);
        d1 += __shfl_down_sync(0xFFFFFFFFu, d1, off);
        s2 += __shfl_down_sync(0xFFFFFFFFu, s2, off);
        d2 += __shfl_down_sync(0xFFFFFFFFu, d2, off);
        s3 += __shfl_down_sync(0xFFFFFFFFu, s3, off);
        d3 += __shfl_down_sync(0xFFFFFFFFu, d3, off);
    }
    if (lane == 0) {
        float b0 = __ldg(b);
        g_s_h[base] = __float2half(s0);
        g_d[base]   = d0 + b0;
        if (h1) { g_s_h[n1] = __float2half(s1); g_d[n1] = d1 + b0; }
        if (h2) { g_s_h[n2] = __float2half(s2); g_d[n2] = d2 + b0; }
        if (h3) { g_s_h[n3] = __float2half(s3); g_d[n3] = d3 + b0; }
    }
}

// Kernel 2: fp16 s-table pulled into smem by ONE cp.async.bulk (TMA bulk copy,
// async proxy — no L1tex wavefronts, no warp time). While it flies, all 1024
// threads issue index loads + fp32 d-gathers (the real wavefront cost). After
// an mbarrier acquire-wait, s comes from LDS; sigmoid; coalesced stores.
__global__ void __launch_bounds__(EBLK, 1)
edge_score_smem_kernel(const int* __restrict__ src,
                       const int* __restrict__ dst,
                       float* __restrict__ out,
                       int n_edges) {
    extern __shared__ char smem_raw[];
    __half* s_sh = reinterpret_cast<__half*>(smem_raw + SMEM_TABLE_OFF);
    uint32_t mbar = smem_u32(smem_raw);

    int tid = threadIdx.x;

    // Init mbarrier + kick the bulk copy from one thread.
    if (tid == 0) {
        asm volatile("mbarrier.init.shared.b64 [%0], 1;" :: "r"(mbar) : "memory");
    }
    __syncthreads();
    if (tid == 0) {
        asm volatile("mbarrier.arrive.expect_tx.shared.b64 _, [%0], %1;"
                     :: "r"(mbar), "r"((uint32_t)TABLE_BYTES) : "memory");
        asm volatile(
            "cp.async.bulk.shared::cta.global.mbarrier::complete_tx::bytes [%0], [%1], %2, [%3];"
            :: "r"(smem_u32(s_sh)), "l"((const void*)g_s_h),
               "r"((uint32_t)TABLE_BYTES), "r"(mbar) : "memory");
    }

    int gtid = blockIdx.x * EBLK + tid;
    int stride = gridDim.x * EBLK;

    int   si[EPT];
    float dv[EPT];

    // Phase A: index loads + d-gathers, issued while the TMA copy is in flight.
    #pragma unroll
    for (int k = 0; k < EPT; k++) {
        int e = gtid + k * stride;
        bool ok = e < n_edges;
        si[k]  = ok ? __ldcs(src + e) : 0;
        int di = ok ? __ldcs(dst + e) : 0;
        dv[k]  = __ldg(g_d + di);
    }

    // Wait for the table (acquire orders the LDS reads below).
    asm volatile(
        "{\n\t.reg .pred P;\n\t"
        "WAIT_%=:\n\t"
        "mbarrier.try_wait.parity.acquire.cta.shared::cta.b64 P, [%0], 0, 0x989680;\n\t"
        "@!P bra WAIT_%=;\n\t}"
        :: "r"(mbar) : "memory");

    // Phase C: LDS s-gathers + sigmoid + coalesced stores.
    #pragma unroll
    for (int k = 0; k < EPT; k++) {
        int e = gtid + k * stride;
        if (e < n_edges) {
            float logit = __half2float(s_sh[si[k]]) + dv[k];
            out[e] = 1.0f / (1.0f + __expf(-logit));
        }
    }
}

extern "C" void kernel_launch(void* const* d_in, const int* in_sizes, int n_in,
                              void* d_out, int out_size) {
    const float* x   = (const float*)d_in[0];
    const int*   src = (const int*)d_in[1];
    const int*   dst = (const int*)d_in[2];
    const float* W   = (const float*)d_in[3];
    const float* b   = (const float*)d_in[4];
    float*       out = (float*)d_out;

    int n_nodes = in_sizes[0] / D;
    int n_edges = in_sizes[1];

    // Kernel 1: 4 nodes per warp, 8 warps/block -> 32 nodes/block
    {
        int nodes_per_block = 8 * 4;
        int blocks = (n_nodes + nodes_per_block - 1) / nodes_per_block;
        node_dots_kernel<<<blocks, 256>>>((const float4*)x, W, b, n_nodes);
    }
    // Kernel 2: smem-table edge scoring, one CTA per SM (200KB smem each)
    {
        cudaFuncSetAttribute(edge_score_smem_kernel,
                             cudaFuncAttributeMaxDynamicSharedMemorySize,
                             SMEM_TOTAL);
        long long cap = (long long)EBLK * EPT;
        int blocks = (int)((n_edges + cap - 1) / cap);
        if (blocks < 148) blocks = 148;
        edge_score_smem_kernel<<<blocks, EBLK, SMEM_TOTAL>>>(src, dst, out, n_edges);
    }
}

// round 8
// speedup vs baseline: 1.1825x; 1.1825x over previous
#include <cuda_runtime.h>
#include <cuda_fp16.h>
#include <cstdint>

#define MAX_NODES 100000
#define D 128

// Per-node projections, both fp16 (400KB total -> ~half fits each SM's L1,
// fully L2-resident). Bias folded into d at the node pass.
__device__ __half g_s_h[MAX_NODES];
__device__ __half g_d_h[MAX_NODES];

// Kernel 1: 4 nodes per warp, all loads issued up-front for MLP=4.
__global__ void node_dots_kernel(const float4* __restrict__ x4,
                                 const float* __restrict__ W,
                                 const float* __restrict__ b,
                                 int n_nodes) {
    __shared__ float4 ws4[32];
    __shared__ float4 wd4[32];
    int tid = threadIdx.x;
    if (tid < 32) ws4[tid] = ((const float4*)W)[tid];
    else if (tid < 64) wd4[tid - 32] = ((const float4*)W)[tid - 32 + 32];
    __syncthreads();

    int lane = tid & 31;
    int gwarp = (blockIdx.x * blockDim.x + tid) >> 5;
    int base = gwarp * 4;
    if (base >= n_nodes) return;

    float4 a = ws4[lane];
    float4 c = wd4[lane];

    int n1 = base + 1, n2 = base + 2, n3 = base + 3;
    bool h1 = n1 < n_nodes, h2 = n2 < n_nodes, h3 = n3 < n_nodes;
    float4 v0 = x4[(size_t)base * 32 + lane];
    float4 v1 = h1 ? x4[(size_t)n1 * 32 + lane] : make_float4(0.f, 0.f, 0.f, 0.f);
    float4 v2 = h2 ? x4[(size_t)n2 * 32 + lane] : make_float4(0.f, 0.f, 0.f, 0.f);
    float4 v3 = h3 ? x4[(size_t)n3 * 32 + lane] : make_float4(0.f, 0.f, 0.f, 0.f);

    float s0 = v0.x * a.x + v0.y * a.y + v0.z * a.z + v0.w * a.w;
    float d0 = v0.x * c.x + v0.y * c.y + v0.z * c.z + v0.w * c.w;
    float s1 = v1.x * a.x + v1.y * a.y + v1.z * a.z + v1.w * a.w;
    float d1 = v1.x * c.x + v1.y * c.y + v1.z * c.z + v1.w * c.w;
    float s2 = v2.x * a.x + v2.y * a.y + v2.z * a.z + v2.w * a.w;
    float d2 = v2.x * c.x + v2.y * c.y + v2.z * c.z + v2.w * c.w;
    float s3 = v3.x * a.x + v3.y * a.y + v3.z * a.z + v3.w * a.w;
    float d3 = v3.x * c.x + v3.y * c.y + v3.z * c.z + v3.w * c.w;

    #pragma unroll
    for (int off = 16; off > 0; off >>= 1) {
        s0 += __shfl_down_sync(0xFFFFFFFFu, s0, off);
        d0 += __shfl_down_sync(0xFFFFFFFFu, d0, off);
        s1 += __shfl_down_sync(0xFFFFFFFFu, s1, off);
        d1 += __shfl_down_sync(0xFFFFFFFFu, d1, off);
        s2 += __shfl_down_sync(0xFFFFFFFFu, s2, off);
        d2 += __shfl_down_sync(0xFFFFFFFFu, d2, off);
        s3 += __shfl_down_sync(0xFFFFFFFFu, s3, off);
        d3 += __shfl_down_sync(0xFFFFFFFFu, d3, off);
    }
    if (lane == 0) {
        float b0 = __ldg(b);
        g_s_h[base] = __float2half(s0);
        g_d_h[base] = __float2half(d0 + b0);
        if (h1) { g_s_h[n1] = __float2half(s1); g_d_h[n1] = __float2half(d1 + b0); }
        if (h2) { g_s_h[n2] = __float2half(s2); g_d_h[n2] = __float2half(d2 + b0); }
        if (h3) { g_s_h[n3] = __float2half(s3); g_d_h[n3] = __float2half(d3 + b0); }
    }
}

__device__ __forceinline__ float sigmoidf_fast(float z) {
    return 1.0f / (1.0f + __expf(-z));
}

// Kernel 2: 4 edges per thread. int4 index loads (evict-first to protect
// table lines), 8 independent 2B gathers into fp16 tables (hot in L1),
// float4 store. Full 228KB L1 available (no smem).
__global__ void edge_score4_kernel(const int4* __restrict__ src4,
                                   const int4* __restrict__ dst4,
                                   float4* __restrict__ out4,
                                   int n_quads) {
    int q = blockIdx.x * blockDim.x + threadIdx.x;
    if (q >= n_quads) return;

    int4 s = __ldcs(src4 + q);
    int4 d = __ldcs(dst4 + q);

    // 8 independent gathers (cached: table lines have ~8x per-SM reuse)
    float s0 = __half2float(g_s_h[s.x]);
    float s1 = __half2float(g_s_h[s.y]);
    float s2 = __half2float(g_s_h[s.z]);
    float s3 = __half2float(g_s_h[s.w]);
    float d0 = __half2float(g_d_h[d.x]);
    float d1 = __half2float(g_d_h[d.y]);
    float d2 = __half2float(g_d_h[d.z]);
    float d3 = __half2float(g_d_h[d.w]);

    float4 o;
    o.x = sigmoidf_fast(s0 + d0);
    o.y = sigmoidf_fast(s1 + d1);
    o.z = sigmoidf_fast(s2 + d2);
    o.w = sigmoidf_fast(s3 + d3);
    __stcs(out4 + q, o);
}

// Tail kernel for n_edges % 4 != 0 (not hit for 1e6 edges, but keep correct)
__global__ void edge_score_tail_kernel(const int* __restrict__ src,
                                       const int* __restrict__ dst,
                                       float* __restrict__ out,
                                       int start, int n_edges) {
    int e = start + blockIdx.x * blockDim.x + threadIdx.x;
    if (e >= n_edges) return;
    float logit = __half2float(g_s_h[src[e]]) + __half2float(g_d_h[dst[e]]);
    out[e] = 1.0f / (1.0f + __expf(-logit));
}

extern "C" void kernel_launch(void* const* d_in, const int* in_sizes, int n_in,
                              void* d_out, int out_size) {
    const float* x   = (const float*)d_in[0];
    const int*   src = (const int*)d_in[1];
    const int*   dst = (const int*)d_in[2];
    const float* W   = (const float*)d_in[3];
    const float* b   = (const float*)d_in[4];
    float*       out = (float*)d_out;

    int n_nodes = in_sizes[0] / D;
    int n_edges = in_sizes[1];

    // Kernel 1: 4 nodes per warp, 8 warps/block -> 32 nodes/block
    {
        int nodes_per_block = 8 * 4;
        int blocks = (n_nodes + nodes_per_block - 1) / nodes_per_block;
        node_dots_kernel<<<blocks, 256>>>((const float4*)x, W, b, n_nodes);
    }
    // Kernel 2: 4 edges per thread, 256-thread blocks
    {
        int n_quads = n_edges / 4;
        int threads = 256;
        int blocks = (n_quads + threads - 1) / threads;
        if (blocks > 0)
            edge_score4_kernel<<<blocks, threads>>>((const int4*)src, (const int4*)dst,
                                                    (float4*)out, n_quads);
        int tail_start = n_quads * 4;
        int tail = n_edges - tail_start;
        if (tail > 0)
            edge_score_tail_kernel<<<1, 32>>>(src, dst, out, tail_start, n_edges);
    }
}

// round 9
// speedup vs baseline: 1.3088x; 1.1068x over previous
#include <cuda_runtime.h>
#include <cuda_fp16.h>
#include <cstdint>

#define MAX_NODES 100000
#define D 128
#define EPT 7           // edges per thread (edge kernel)
#define EBLK 1024       // threads per block (edge kernel)

#define TABLE_BYTES (MAX_NODES * 2)      // one fp16 table = 200000 B
#define SMEM_TABLE_OFF 16                // mbarrier at 0, table at 16
#define SMEM_TOTAL (SMEM_TABLE_OFF + TABLE_BYTES)

// Per-node projections, both fp16, 16B-aligned for packed stores.
// Bias folded into d at the node pass.
__device__ __align__(16) __half g_s_h[MAX_NODES];
__device__ __align__(16) __half g_d_h[MAX_NODES];

__device__ __forceinline__ uint32_t smem_u32(const void* p) {
    uint32_t a;
    asm("{ .reg .u64 t; cvta.to.shared.u64 t, %1; cvt.u32.u64 %0, t; }" : "=r"(a) : "l"(p));
    return a;
}

__device__ __forceinline__ float sigmoidf_fast(float z) {
    return 1.0f / (1.0f + __expf(-z));
}

// Kernel 1: 8 nodes per warp, all 8 LDG.128 issued up-front (4KB in flight
// per warp). Shuffle reductions hidden under memory latency. Lane 0 writes
// the 8 fp16 results per table as one 16B store.
__global__ void node_dots_kernel(const float4* __restrict__ x4,
                                 const float* __restrict__ W,
                                 const float* __restrict__ b,
                                 int n_nodes) {
    __shared__ float4 ws4[32];
    __shared__ float4 wd4[32];
    int tid = threadIdx.x;
    if (tid < 32) ws4[tid] = ((const float4*)W)[tid];
    else if (tid < 64) wd4[tid - 32] = ((const float4*)W)[tid - 32 + 32];
    __syncthreads();

    int lane = tid & 31;
    int gwarp = (blockIdx.x * blockDim.x + tid) >> 5;
    int base = gwarp * 8;
    if (base >= n_nodes) return;

    float4 a = ws4[lane];
    float4 c = wd4[lane];
    float b0 = __ldg(b);

    float sv[8], dv[8];

    if (base + 8 <= n_nodes) {
        float4 v[8];
        #pragma unroll
        for (int i = 0; i < 8; i++)
            v[i] = x4[(size_t)(base + i) * 32 + lane];
        #pragma unroll
        for (int i = 0; i < 8; i++) {
            sv[i] = v[i].x * a.x + v[i].y * a.y + v[i].z * a.z + v[i].w * a.w;
            dv[i] = v[i].x * c.x + v[i].y * c.y + v[i].z * c.z + v[i].w * c.w;
        }
        #pragma unroll
        for (int off = 16; off > 0; off >>= 1) {
            #pragma unroll
            for (int i = 0; i < 8; i++) {
                sv[i] += __shfl_down_sync(0xFFFFFFFFu, sv[i], off);
                dv[i] += __shfl_down_sync(0xFFFFFFFFu, dv[i], off);
            }
        }
        if (lane == 0) {
            __half hs[8], hd[8];
            #pragma unroll
            for (int i = 0; i < 8; i++) {
                hs[i] = __float2half(sv[i]);
                hd[i] = __float2half(dv[i] + b0);
            }
            *reinterpret_cast<uint4*>(&g_s_h[base]) = *reinterpret_cast<uint4*>(hs);
            *reinterpret_cast<uint4*>(&g_d_h[base]) = *reinterpret_cast<uint4*>(hd);
        }
    } else {
        // Tail: per-node guarded (not hit for 100000 nodes, kept for safety)
        for (int i = 0; i < 8; i++) {
            int n = base + i;
            if (n >= n_nodes) break;
            float4 v = x4[(size_t)n * 32 + lane];
            float s = v.x * a.x + v.y * a.y + v.z * a.z + v.w * a.w;
            float d = v.x * c.x + v.y * c.y + v.z * c.z + v.w * c.w;
            #pragma unroll
            for (int off = 16; off > 0; off >>= 1) {
                s += __shfl_down_sync(0xFFFFFFFFu, s, off);
                d += __shfl_down_sync(0xFFFFFFFFu, d, off);
            }
            if (lane == 0) {
                g_s_h[n] = __float2half(s);
                g_d_h[n] = __float2half(d + b0);
            }
        }
    }
}

// Kernel 2: table-swap edge scoring. One 200KB smem buffer, filled twice by
// TMA bulk copies (async proxy, no L1tex work): first the s-table (gather s
// into registers via LDS), then the d-table (gather d, sigmoid, store).
// All 2e6 gathers are LDS (~4 cyc/warp-instr) instead of L1tex replays
// (~66 cyc/warp-instr).
__global__ void __launch_bounds__(EBLK, 1)
edge_score_swap_kernel(const int* __restrict__ src,
                       const int* __restrict__ dst,
                       float* __restrict__ out,
                       int n_edges) {
    extern __shared__ char smem_raw[];
    __half* tab = reinterpret_cast<__half*>(smem_raw + SMEM_TABLE_OFF);
    uint32_t mbar = smem_u32(smem_raw);
    uint32_t tab_a = smem_u32(tab);

    int tid = threadIdx.x;

    if (tid == 0) {
        asm volatile("mbarrier.init.shared.b64 [%0], 1;" :: "r"(mbar) : "memory");
    }
    __syncthreads();
    // Broadcast 1: s-table
    if (tid == 0) {
        asm volatile("mbarrier.arrive.expect_tx.shared.b64 _, [%0], %1;"
                     :: "r"(mbar), "r"((uint32_t)TABLE_BYTES) : "memory");
        asm volatile(
            "cp.async.bulk.shared::cta.global.mbarrier::complete_tx::bytes [%0], [%1], %2, [%3];"
            :: "r"(tab_a), "l"((const void*)g_s_h),
               "r"((uint32_t)TABLE_BYTES), "r"(mbar) : "memory");
    }

    int gtid = blockIdx.x * EBLK + tid;
    int stride = gridDim.x * EBLK;

    // Index loads in flight while broadcast 1 flies.
    int si[EPT], di[EPT];
    #pragma unroll
    for (int k = 0; k < EPT; k++) {
        int e = gtid + k * stride;
        bool ok = e < n_edges;
        si[k] = ok ? __ldcs(src + e) : 0;
        di[k] = ok ? __ldcs(dst + e) : 0;
    }

    // Wait table 1 (phase parity 0)
    asm volatile(
        "{\n\t.reg .pred P;\n\t"
        "W0_%=:\n\t"
        "mbarrier.try_wait.parity.acquire.cta.shared::cta.b64 P, [%0], 0, 0x989680;\n\t"
        "@!P bra W0_%=;\n\t}"
        :: "r"(mbar) : "memory");

    float part[EPT];
    #pragma unroll
    for (int k = 0; k < EPT; k++)
        part[k] = __half2float(tab[si[k]]);

    // All phase-S reads done before the buffer is overwritten.
    __syncthreads();
    // Broadcast 2: d-table (generic->async proxy ordering via fence)
    if (tid == 0) {
        asm volatile("fence.proxy.async.shared::cta;" ::: "memory");
        asm volatile("mbarrier.arrive.expect_tx.shared.b64 _, [%0], %1;"
                     :: "r"(mbar), "r"((uint32_t)TABLE_BYTES) : "memory");
        asm volatile(
            "cp.async.bulk.shared::cta.global.mbarrier::complete_tx::bytes [%0], [%1], %2, [%3];"
            :: "r"(tab_a), "l"((const void*)g_d_h),
               "r"((uint32_t)TABLE_BYTES), "r"(mbar) : "memory");
    }

    // Wait table 2 (phase parity 1)
    asm volatile(
        "{\n\t.reg .pred P;\n\t"
        "W1_%=:\n\t"
        "mbarrier.try_wait.parity.acquire.cta.shared::cta.b64 P, [%0], 1, 0x989680;\n\t"
        "@!P bra W1_%=;\n\t}"
        :: "r"(mbar) : "memory");

    #pragma unroll
    for (int k = 0; k < EPT; k++) {
        int e = gtid + k * stride;
        if (e < n_edges) {
            float logit = part[k] + __half2float(tab[di[k]]);
            __stcs(out + e, sigmoidf_fast(logit));
        }
    }
}

extern "C" void kernel_launch(void* const* d_in, const int* in_sizes, int n_in,
                              void* d_out, int out_size) {
    const float* x   = (const float*)d_in[0];
    const int*   src = (const int*)d_in[1];
    const int*   dst = (const int*)d_in[2];
    const float* W   = (const float*)d_in[3];
    const float* b   = (const float*)d_in[4];
    float*       out = (float*)d_out;

    int n_nodes = in_sizes[0] / D;
    int n_edges = in_sizes[1];

    // Kernel 1: 8 nodes per warp, 8 warps/block -> 64 nodes/block
    {
        int nodes_per_block = 8 * 8;
        int blocks = (n_nodes + nodes_per_block - 1) / nodes_per_block;
        node_dots_kernel<<<blocks, 256>>>((const float4*)x, W, b, n_nodes);
    }
    // Kernel 2: table-swap edge scoring (single wave of <=148 CTAs)
    {
        static bool attr_set = false;
        if (!attr_set) {
            cudaFuncSetAttribute(edge_score_swap_kernel,
                                 cudaFuncAttributeMaxDynamicSharedMemorySize,
                                 SMEM_TOTAL);
            attr_set = true;
        }
        long long per_blk = (long long)EBLK * EPT;
        int blocks = (int)((n_edges + per_blk - 1) / per_blk);  // 140 for 1e6
        edge_score_swap_kernel<<<blocks, EBLK, SMEM_TOTAL>>>(src, dst, out, n_edges);
    }
}

// round 10
// speedup vs baseline: 1.3266x; 1.0135x over previous
#include <cuda_runtime.h>
#include <cuda_fp16.h>
#include <cstdint>

#define MAX_NODES 100000
#define D 128
#define EPT 14          // edges per thread (edge kernel)
#define EBLK 1024       // threads per block (edge kernel)

#define TABLE_BYTES (MAX_NODES * 2)      // one fp16 table = 200000 B
#define SMEM_TABLE_OFF 16                // mbarrier at 0, table at 16
#define SMEM_TOTAL (SMEM_TABLE_OFF + TABLE_BYTES)

// Per-node projections, both fp16. Bias folded into d at the node pass.
__device__ __align__(16) __half g_s_h[MAX_NODES];
__device__ __align__(16) __half g_d_h[MAX_NODES];

__device__ __forceinline__ uint32_t smem_u32(const void* p) {
    uint32_t a;
    asm("{ .reg .u64 t; cvta.to.shared.u64 t, %1; cvt.u32.u64 %0, t; }" : "=r"(a) : "l"(p));
    return a;
}

__device__ __forceinline__ float sigmoidf_fast(float z) {
    return 1.0f / (1.0f + __expf(-z));
}

// Kernel 1: 4 nodes per warp via 8-lane subgroups. Each lane accumulates
// 4 float4 chunks (row covered by 8 lanes x 4 iters), then a 3-round
// subgroup shuffle reduction (all 4 nodes reduced in the same instructions).
// Shuffle cost: 6 SHFL per 4 nodes (vs 80 per 8 nodes before).
__global__ void node_dots_kernel(const float4* __restrict__ x4,
                                 const float* __restrict__ W,
                                 const float* __restrict__ b,
                                 int n_nodes) {
    __shared__ float4 ws4[32];
    __shared__ float4 wd4[32];
    int tid = threadIdx.x;
    if (tid < 32) ws4[tid] = ((const float4*)W)[tid];
    else if (tid < 64) wd4[tid - 32] = ((const float4*)W)[tid - 32 + 32];
    __syncthreads();

    int lane = tid & 31;
    int g    = lane & 7;     // position within 8-lane group
    int sub  = lane >> 3;    // which of the warp's 4 nodes
    int warpId = (blockIdx.x * blockDim.x + tid) >> 5;
    int node = warpId * 4 + sub;
    if (node >= n_nodes) return;

    const float4* row = x4 + (size_t)node * 32;
    float s = 0.f, d = 0.f;
    #pragma unroll
    for (int it = 0; it < 4; it++) {
        float4 v = row[it * 8 + g];
        float4 a = ws4[it * 8 + g];
        float4 c = wd4[it * 8 + g];
        s += v.x * a.x + v.y * a.y + v.z * a.z + v.w * a.w;
        d += v.x * c.x + v.y * c.y + v.z * c.z + v.w * c.w;
    }

    // 3-round reduction within each 8-lane group
    #pragma unroll
    for (int off = 4; off > 0; off >>= 1) {
        s += __shfl_down_sync(0xFFFFFFFFu, s, off);
        d += __shfl_down_sync(0xFFFFFFFFu, d, off);
    }
    if (g == 0) {
        float b0 = __ldg(b);
        g_s_h[node] = __float2half(s);
        g_d_h[node] = __float2half(d + b0);
    }
}

// Kernel 2: table-swap edge scoring. 70 CTAs (broadcast traffic = grid x
// 200KB x 2 shares the chip TMA/LTS cap, so a smaller single-wave grid
// halves broadcast time; the LDS phases stay cheap). One 200KB smem buffer
// filled twice by TMA bulk copies; all 2e6 gathers are LDS.
__global__ void __launch_bounds__(EBLK, 1)
edge_score_swap_kernel(const int* __restrict__ src,
                       const int* __restrict__ dst,
                       float* __restrict__ out,
                       int n_edges) {
    extern __shared__ char smem_raw[];
    __half* tab = reinterpret_cast<__half*>(smem_raw + SMEM_TABLE_OFF);
    uint32_t mbar = smem_u32(smem_raw);
    uint32_t tab_a = smem_u32(tab);

    int tid = threadIdx.x;

    if (tid == 0) {
        asm volatile("mbarrier.init.shared.b64 [%0], 1;" :: "r"(mbar) : "memory");
    }
    __syncthreads();
    // Broadcast 1: s-table
    if (tid == 0) {
        asm volatile("mbarrier.arrive.expect_tx.shared.b64 _, [%0], %1;"
                     :: "r"(mbar), "r"((uint32_t)TABLE_BYTES) : "memory");
        asm volatile(
            "cp.async.bulk.shared::cta.global.mbarrier::complete_tx::bytes [%0], [%1], %2, [%3];"
            :: "r"(tab_a), "l"((const void*)g_s_h),
               "r"((uint32_t)TABLE_BYTES), "r"(mbar) : "memory");
    }

    int gtid = blockIdx.x * EBLK + tid;
    int stride = gridDim.x * EBLK;

    // Index loads in flight while broadcast 1 flies.
    int si[EPT], di[EPT];
    #pragma unroll
    for (int k = 0; k < EPT; k++) {
        int e = gtid + k * stride;
        bool ok = e < n_edges;
        si[k] = ok ? __ldcs(src + e) : 0;
        di[k] = ok ? __ldcs(dst + e) : 0;
    }

    // Wait table 1 (phase parity 0)
    asm volatile(
        "{\n\t.reg .pred P;\n\t"
        "W0_%=:\n\t"
        "mbarrier.try_wait.parity.acquire.cta.shared::cta.b64 P, [%0], 0, 0x989680;\n\t"
        "@!P bra W0_%=;\n\t}"
        :: "r"(mbar) : "memory");

    float part[EPT];
    #pragma unroll
    for (int k = 0; k < EPT; k++)
        part[k] = __half2float(tab[si[k]]);

    // All phase-S reads done before the buffer is overwritten.
    __syncthreads();
    // Broadcast 2: d-table (generic->async proxy ordering via fence)
    if (tid == 0) {
        asm volatile("fence.proxy.async.shared::cta;" ::: "memory");
        asm volatile("mbarrier.arrive.expect_tx.shared.b64 _, [%0], %1;"
                     :: "r"(mbar), "r"((uint32_t)TABLE_BYTES) : "memory");
        asm volatile(
            "cp.async.bulk.shared::cta.global.mbarrier::complete_tx::bytes [%0], [%1], %2, [%3];"
            :: "r"(tab_a), "l"((const void*)g_d_h),
               "r"((uint32_t)TABLE_BYTES), "r"(mbar) : "memory");
    }

    // Wait table 2 (phase parity 1)
    asm volatile(
        "{\n\t.reg .pred P;\n\t"
        "W1_%=:\n\t"
        "mbarrier.try_wait.parity.acquire.cta.shared::cta.b64 P, [%0], 1, 0x989680;\n\t"
        "@!P bra W1_%=;\n\t}"
        :: "r"(mbar) : "memory");

    #pragma unroll
    for (int k = 0; k < EPT; k++) {
        int e = gtid + k * stride;
        if (e < n_edges) {
            float logit = part[k] + __half2float(tab[di[k]]);
            __stcs(out + e, sigmoidf_fast(logit));
        }
    }
}

extern "C" void kernel_launch(void* const* d_in, const int* in_sizes, int n_in,
                              void* d_out, int out_size) {
    const float* x   = (const float*)d_in[0];
    const int*   src = (const int*)d_in[1];
    const int*   dst = (const int*)d_in[2];
    const float* W   = (const float*)d_in[3];
    const float* b   = (const float*)d_in[4];
    float*       out = (float*)d_out;

    int n_nodes = in_sizes[0] / D;
    int n_edges = in_sizes[1];

    // Kernel 1: 4 nodes per warp, 8 warps/block -> 32 nodes/block
    {
        int nodes_per_block = 8 * 4;
        int blocks = (n_nodes + nodes_per_block - 1) / nodes_per_block;
        node_dots_kernel<<<blocks, 256>>>((const float4*)x, W, b, n_nodes);
    }
    // Kernel 2: table-swap edge scoring, small single-wave grid (~70 CTAs)
    {
        static bool attr_set = false;
        if (!attr_set) {
            cudaFuncSetAttribute(edge_score_swap_kernel,
                                 cudaFuncAttributeMaxDynamicSharedMemorySize,
                                 SMEM_TOTAL);
            attr_set = true;
        }
        long long per_blk = (long long)EBLK * EPT;
        int blocks = (int)((n_edges + per_blk - 1) / per_blk);  // 70 for 1e6
        edge_score_swap_kernel<<<blocks, EBLK, SMEM_TOTAL>>>(src, dst, out, n_edges);
    }
}